// round 15
// baseline (speedup 1.0000x reference)
#include <cuda_runtime.h>
#include <cuda_fp16.h>
#include <math.h>

// Problem constants
#define Nn   100000
#define Tt   64
#define Ee   1000000
#define ETOT (Ee + Nn)    // edges + self loops
#define NB   32           // nodes per LSTM block
#define HW   36           // hsh row stride in 32-bit words
#define HS   (NB * HW)    // one h buffer in words

// -------- scratch (device globals; no allocations allowed) ----------
__device__ __half2 g_xh2[Nn * 64];   // GAT features, word p = (head p/32, dims 2p%64)
__device__ __half2 g_acc2[Nn * 64];  // weighted message accumulator (fp16x2)
__device__ float   g_asrc[Nn * 2];
__device__ float   g_adst[Nn * 2];
__device__ float   g_z[Nn * 2];      // segment sum (fp32)
__device__ int     g_estride;        // 1 if edge_index is int32, 2 if int64
__device__ int     g_eoff;           // offset (in int32 words) of dst row

// ==================== edge dtype probe =============================
__global__ void detect_kernel(const int* __restrict__ ei32)
{
    if (threadIdx.x == 0 && blockIdx.x == 0) {
        bool all0 = true;
        #pragma unroll
        for (int i = 1; i < 64; i += 2) all0 &= (ei32[i] == 0);
        g_estride = all0 ? 2 : 1;
        g_eoff    = all0 ? 2 * Ee : Ee;
    }
}

// ==================== helpers ======================================
__device__ __forceinline__ unsigned tanh2(unsigned x)
{
    unsigned y;
    asm("tanh.approx.f16x2 %0, %1;" : "=r"(y) : "r"(x));
    return y;
}
__device__ __forceinline__ __half2 u2h(unsigned u) { return *reinterpret_cast<__half2*>(&u); }
__device__ __forceinline__ unsigned h2u(__half2 h) { return *reinterpret_cast<unsigned*>(&h); }

// fp16x2 sigmoid: 0.5 + 0.5*tanh(0.5*x)
__device__ __forceinline__ __half2 sig2(unsigned u, __half2 half05)
{
    __half2 x = __hmul2(u2h(u), half05);
    return __hfma2(u2h(tanh2(h2u(x))), half05, half05);
}

__device__ __forceinline__ unsigned f2h2u(float a, float b)
{
    __half2 h = __floats2half2_rn(a, b);
    return *reinterpret_cast<unsigned*>(&h);
}

// m16n8k16, fp16 in / fp16 accum. D regs = 2x fp16x2 (rows grp, grp+8).
__device__ __forceinline__ void mma_f16acc(unsigned& c0, unsigned& c1,
                                           unsigned a0, unsigned a1, unsigned a2, unsigned a3,
                                           unsigned b0, unsigned b1)
{
    asm("mma.sync.aligned.m16n8k16.row.col.f16.f16.f16.f16 "
        "{%0,%1}, {%2,%3,%4,%5}, {%6,%7}, {%0,%1};"
        : "+r"(c0), "+r"(c1)
        : "r"(a0), "r"(a1), "r"(a2), "r"(a3), "r"(b0), "r"(b1));
}

// m16n8k16, fp16 in / fp32 accum.
__device__ __forceinline__ void mma_f32acc(float& c0, float& c1, float& c2, float& c3,
                                           unsigned a0, unsigned a1, unsigned a2, unsigned a3,
                                           unsigned b0, unsigned b1)
{
    asm("mma.sync.aligned.m16n8k16.row.col.f32.f16.f16.f32 "
        "{%0,%1,%2,%3}, {%4,%5,%6,%7}, {%8,%9}, {%0,%1,%2,%3};"
        : "+f"(c0), "+f"(c1), "+f"(c2), "+f"(c3)
        : "r"(a0), "r"(a1), "r"(a2), "r"(a3), "r"(b0), "r"(b1));
}

// ==================== LSTM + fused GAT transform ===================
// 256 threads = 8 warps, 32 nodes/block. Main loop: fp16 m16n8k16
// recurrence at the fallback-HMMA ceiling; t=0 MMAs skipped (h0=0).
// Epilogue: final h (in MMA A-layout in smem) -> xh = h @ gat_w^T
// via fp32-accum MMAs + attention dots.
__global__ void __launch_bounds__(256, 2)
lstm_kernel(const float* __restrict__ x, const float* __restrict__ w_ih,
            const float* __restrict__ w_hh, const float* __restrict__ b_ih,
            const float* __restrict__ b_hh, const float* __restrict__ gat_w,
            const float* __restrict__ att_src, const float* __restrict__ att_dst)
{
    __shared__ unsigned xsh[Tt * NB * 2];   // broadcast half2 per (t, n, d)
    __shared__ unsigned hsh[2 * HS];        // double-buffered h, fp16x2 words
    __shared__ float    sm_as[2][NB];       // attention partial sums
    __shared__ float    sm_ad[2][NB];

    const int tid  = threadIdx.x;
    const int base = blockIdx.x * NB;
    const int wid  = tid >> 5, lane = tid & 31;
    const int grp  = lane >> 2, tig = lane & 3;

    for (int i = tid; i < NB * Tt * 2; i += 256) {
        int n = i >> 7;
        int r = i & 127;
        float v = x[(size_t)(base + n) * 128 + r];
        xsh[(r >> 1) * (NB * 2) + n * 2 + (r & 1)] = h2u(__float2half2_rn(v));
    }
    if (tid < 64) {
        sm_as[tid >> 5][tid & 31] = 0.f;
        sm_ad[tid >> 5][tid & 31] = 0.f;
    }

    const int j0 = wid * 8 + 2 * tig;

    unsigned bias2[4], wa2[4], wb2[4];
    #pragma unroll
    for (int q = 0; q < 4; ++q) {
        int g = q * 64 + j0;
        bias2[q] = f2h2u(b_ih[g] + b_hh[g], b_ih[g + 1] + b_hh[g + 1]);
        wa2[q]   = f2h2u(w_ih[g * 2],     w_ih[(g + 1) * 2]);
        wb2[q]   = f2h2u(w_ih[g * 2 + 1], w_ih[(g + 1) * 2 + 1]);
    }

    unsigned bf[4][4][2];
    #pragma unroll
    for (int q = 0; q < 4; ++q) {
        const float* wr = &w_hh[(size_t)(q * 64 + wid * 8 + grp) * 64];
        #pragma unroll
        for (int kt = 0; kt < 4; ++kt) {
            int k = kt * 16 + 2 * tig;
            bf[q][kt][0] = f2h2u(wr[k],     wr[k + 1]);
            bf[q][kt][1] = f2h2u(wr[k + 8], wr[k + 9]);
        }
    }

    const int rp[4] = { grp * HW + tig,        (grp + 8) * HW + tig,
                        (grp + 16) * HW + tig, (grp + 24) * HW + tig };
    const int sp[4] = { grp * HW + wid * 4 + tig,        (grp + 8) * HW + wid * 4 + tig,
                        (grp + 16) * HW + wid * 4 + tig, (grp + 24) * HW + wid * 4 + tig };

    const __half2 half05 = __float2half2_rn(0.5f);
    __half2 creg[4];
    #pragma unroll
    for (int r = 0; r < 4; ++r) creg[r] = __float2half2_rn(0.f);

    __syncthreads();

    for (int t = 0; t < Tt; ++t) {
        const unsigned* rb   = &hsh[(t & 1) * HS];
        unsigned*       wbuf = &hsh[((t + 1) & 1) * HS];

        unsigned xl[4], xh[4];
        #pragma unroll
        for (int m = 0; m < 4; ++m) {
            int n = grp + 8 * m;
            xl[m] = xsh[t * (NB * 2) + n * 2];
            xh[m] = xsh[t * (NB * 2) + n * 2 + 1];
        }
        unsigned c[4][4];
        #pragma unroll
        for (int q = 0; q < 4; ++q) {
            #pragma unroll
            for (int m = 0; m < 4; ++m)
                c[q][m] = h2u(__hfma2(u2h(wb2[q]), u2h(xh[m]),
                              __hfma2(u2h(wa2[q]), u2h(xl[m]), u2h(bias2[q]))));
        }
        if (t > 0) {   // h0 = 0 -> step-0 MMAs are all zero, skip
            #pragma unroll
            for (int kt = 0; kt < 4; ++kt) {
                unsigned a0 = rb[rp[0] + kt * 8];
                unsigned a1 = rb[rp[1] + kt * 8];
                unsigned a2 = rb[rp[0] + kt * 8 + 4];
                unsigned a3 = rb[rp[1] + kt * 8 + 4];
                unsigned a4 = rb[rp[2] + kt * 8];
                unsigned a5 = rb[rp[3] + kt * 8];
                unsigned a6 = rb[rp[2] + kt * 8 + 4];
                unsigned a7 = rb[rp[3] + kt * 8 + 4];
                #pragma unroll
                for (int q = 0; q < 4; ++q) {
                    mma_f16acc(c[q][0], c[q][1], a0, a1, a2, a3,
                               bf[q][kt][0], bf[q][kt][1]);
                    mma_f16acc(c[q][2], c[q][3], a4, a5, a6, a7,
                               bf[q][kt][0], bf[q][kt][1]);
                }
            }
        }

        #pragma unroll
        for (int r = 0; r < 4; ++r) {
            __half2 i2 = sig2(c[0][r], half05);
            __half2 f2 = sig2(c[1][r], half05);
            __half2 g2 = u2h(tanh2(c[2][r]));
            __half2 o2 = sig2(c[3][r], half05);
            creg[r] = __hfma2(f2, creg[r], __hmul2(i2, g2));
            wbuf[sp[r]] = h2u(__hmul2(o2, u2h(tanh2(h2u(creg[r])))));
        }
        __syncthreads();
    }

    // ============ fused GAT transform epilogue =====================
    const unsigned* hb = &hsh[0];   // final h buffer (Tt & 1) = 0

    unsigned bg[2][4][2];
    #pragma unroll
    for (int nt = 0; nt < 2; ++nt) {
        const float* wr = &gat_w[(size_t)(wid * 16 + nt * 8 + grp) * 64];
        #pragma unroll
        for (int kt = 0; kt < 4; ++kt) {
            int k = kt * 16 + 2 * tig;
            bg[nt][kt][0] = f2h2u(wr[k],     wr[k + 1]);
            bg[nt][kt][1] = f2h2u(wr[k + 8], wr[k + 9]);
        }
    }

    float cx[2][2][4];
    #pragma unroll
    for (int nt = 0; nt < 2; ++nt)
        #pragma unroll
        for (int mt = 0; mt < 2; ++mt)
            #pragma unroll
            for (int e = 0; e < 4; ++e) cx[nt][mt][e] = 0.f;

    #pragma unroll
    for (int kt = 0; kt < 4; ++kt) {
        unsigned a0 = hb[rp[0] + kt * 8];
        unsigned a1 = hb[rp[1] + kt * 8];
        unsigned a2 = hb[rp[0] + kt * 8 + 4];
        unsigned a3 = hb[rp[1] + kt * 8 + 4];
        unsigned a4 = hb[rp[2] + kt * 8];
        unsigned a5 = hb[rp[3] + kt * 8];
        unsigned a6 = hb[rp[2] + kt * 8 + 4];
        unsigned a7 = hb[rp[3] + kt * 8 + 4];
        #pragma unroll
        for (int nt = 0; nt < 2; ++nt) {
            mma_f32acc(cx[nt][0][0], cx[nt][0][1], cx[nt][0][2], cx[nt][0][3],
                       a0, a1, a2, a3, bg[nt][kt][0], bg[nt][kt][1]);
            mma_f32acc(cx[nt][1][0], cx[nt][1][1], cx[nt][1][2], cx[nt][1][3],
                       a4, a5, a6, a7, bg[nt][kt][0], bg[nt][kt][1]);
        }
    }

    const int hg0  = wid * 16 + 2 * tig;
    const int hg1  = hg0 + 8;
    const int head = wid >> 2;
    const int p0   = head * 32 + ((hg0 & 63) >> 1);
    const int p1   = head * 32 + ((hg1 & 63) >> 1);
    const float2 as0 = make_float2(att_src[hg0], att_src[hg0 + 1]);
    const float2 as1 = make_float2(att_src[hg1], att_src[hg1 + 1]);
    const float2 ad0 = make_float2(att_dst[hg0], att_dst[hg0 + 1]);
    const float2 ad1 = make_float2(att_dst[hg1], att_dst[hg1 + 1]);
    const __half2 hz = __float2half2_rn(0.f);

    #pragma unroll
    for (int mt = 0; mt < 2; ++mt) {
        #pragma unroll
        for (int r = 0; r < 2; ++r) {
            int node = mt * 16 + grp + 8 * r;
            size_t n = base + node;
            float v00 = cx[0][mt][2 * r], v01 = cx[0][mt][2 * r + 1];
            float v10 = cx[1][mt][2 * r], v11 = cx[1][mt][2 * r + 1];
            g_xh2[n * 64 + p0]  = __floats2half2_rn(v00, v01);
            g_xh2[n * 64 + p1]  = __floats2half2_rn(v10, v11);
            g_acc2[n * 64 + p0] = hz;
            g_acc2[n * 64 + p1] = hz;
            float ps = v00 * as0.x + v01 * as0.y + v10 * as1.x + v11 * as1.y;
            float pd = v00 * ad0.x + v01 * ad0.y + v10 * ad1.x + v11 * ad1.y;
            ps += __shfl_xor_sync(0xffffffffu, ps, 1);
            ps += __shfl_xor_sync(0xffffffffu, ps, 2);
            pd += __shfl_xor_sync(0xffffffffu, pd, 1);
            pd += __shfl_xor_sync(0xffffffffu, pd, 2);
            if (tig == 0) {
                atomicAdd(&sm_as[head][node], ps);
                atomicAdd(&sm_ad[head][node], pd);
            }
        }
    }
    __syncthreads();
    if (tid < 64) {
        int node = tid & 31, hd = tid >> 5;
        size_t n = base + node;
        g_asrc[n * 2 + hd] = sm_as[hd][node];
        g_adst[n * 2 + hd] = sm_ad[hd][node];
        g_z[n * 2 + hd]    = 0.f;
    }
}

// ==================== GAT: exp-sum + weighted messages =============
// 8 lanes/edge; each lane owns one 16B chunk per head (2 independent
// v4.f16x2 reduction chains).
__global__ void __launch_bounds__(256)
edge_sum_kernel(const int* __restrict__ ei32)
{
    int e   = (blockIdx.x * 256 + threadIdx.x) >> 3;
    int sub = threadIdx.x & 7;
    if (e >= ETOT) return;
    const int st = g_estride, of = g_eoff;
    int s, d;
    if (e < Ee) { s = ei32[(size_t)e * st]; d = ei32[(size_t)of + (size_t)e * st]; }
    else        { s = d = e - Ee; }

    float e0 = g_asrc[s * 2]     + g_adst[d * 2];
    float e1 = g_asrc[s * 2 + 1] + g_adst[d * 2 + 1];
    e0 = e0 > 0.f ? e0 : 0.2f * e0;
    e1 = e1 > 0.f ? e1 : 0.2f * e1;
    float w0 = __expf(e0);
    float w1 = __expf(e1);
    if (sub == 0) atomicAdd(&g_z[d * 2],     w0);
    if (sub == 1) atomicAdd(&g_z[d * 2 + 1], w1);

    __half2 c0 = __float2half2_rn(w0);
    __half2 c1 = __float2half2_rn(w1);
    const uint4* xb = (const uint4*)(g_xh2 + (size_t)s * 64);
    uint4 xv0 = xb[sub];
    uint4 xv1 = xb[8 + sub];
    unsigned m00 = h2u(__hmul2(u2h(xv0.x), c0));
    unsigned m01 = h2u(__hmul2(u2h(xv0.y), c0));
    unsigned m02 = h2u(__hmul2(u2h(xv0.z), c0));
    unsigned m03 = h2u(__hmul2(u2h(xv0.w), c0));
    unsigned m10 = h2u(__hmul2(u2h(xv1.x), c1));
    unsigned m11 = h2u(__hmul2(u2h(xv1.y), c1));
    unsigned m12 = h2u(__hmul2(u2h(xv1.z), c1));
    unsigned m13 = h2u(__hmul2(u2h(xv1.w), c1));
    __half2* ap0 = g_acc2 + (size_t)d * 64 + sub * 4;
    __half2* ap1 = ap0 + 32;
    asm volatile("red.global.add.noftz.v4.f16x2 [%0], {%1,%2,%3,%4};"
                 :: "l"(ap0), "r"(m00), "r"(m01), "r"(m02), "r"(m03) : "memory");
    asm volatile("red.global.add.noftz.v4.f16x2 [%0], {%1,%2,%3,%4};"
                 :: "l"(ap1), "r"(m10), "r"(m11), "r"(m12), "r"(m13) : "memory");
}

// ==================== finalize (16 lanes/node) =====================
// Lane sub owns words sub, 16+sub (head0) and 32+sub, 48+sub (head1),
// i.e. dim pairs 2sub,2sub+1 and 2(16+sub),2(16+sub)+1. Width-16 shfl.
__global__ void __launch_bounds__(256)
final_kernel(const float* __restrict__ gat_b, const float* __restrict__ lin_w,
             const float* __restrict__ lin_b, float* __restrict__ out)
{
    int idx = blockIdx.x * 256 + threadIdx.x;
    int n   = idx >> 4;
    int sub = idx & 15;
    if (n >= Nn) return;
    float r0 = 0.5f / g_z[n * 2];
    float r1 = 0.5f / g_z[n * 2 + 1];
    const __half2* ac = g_acc2 + (size_t)n * 64;
    float2 a00 = __half22float2(ac[sub]);         // head0, dims 2sub,2sub+1
    float2 a01 = __half22float2(ac[16 + sub]);    // head0, dims 2(16+sub)..
    float2 a10 = __half22float2(ac[32 + sub]);    // head1, dims 2sub..
    float2 a11 = __half22float2(ac[48 + sub]);    // head1, dims 2(16+sub)..
    float2 gb0 = ((const float2*)gat_b)[sub];
    float2 gb1 = ((const float2*)gat_b)[16 + sub];
    float v0 = a00.x * r0 + a10.x * r1 + gb0.x;
    float v1 = a00.y * r0 + a10.y * r1 + gb0.y;
    float v2 = a01.x * r0 + a11.x * r1 + gb1.x;
    float v3 = a01.y * r0 + a11.y * r1 + gb1.y;
    v0 = v0 > 0.f ? v0 : 0.f;
    v1 = v1 > 0.f ? v1 : 0.f;
    v2 = v2 > 0.f ? v2 : 0.f;
    v3 = v3 > 0.f ? v3 : 0.f;
    float2 l00 = ((const float2*)lin_w)[sub];        // row0, dims 2sub..
    float2 l01 = ((const float2*)lin_w)[16 + sub];   // row0, dims 2(16+sub)..
    float2 l10 = ((const float2*)lin_w)[32 + sub];   // row1
    float2 l11 = ((const float2*)lin_w)[48 + sub];
    float y0 = v0 * l00.x + v1 * l00.y + v2 * l01.x + v3 * l01.y;
    float y1 = v0 * l10.x + v1 * l10.y + v2 * l11.x + v3 * l11.y;
    #pragma unroll
    for (int off = 8; off; off >>= 1) {
        y0 += __shfl_down_sync(0xffffffffu, y0, off, 16);
        y1 += __shfl_down_sync(0xffffffffu, y1, off, 16);
    }
    if (sub == 0) {
        out[n * 2]     = 1.f / (1.f + __expf(-(y0 + lin_b[0])));
        out[n * 2 + 1] = 1.f / (1.f + __expf(-(y1 + lin_b[1])));
    }
}

// ==================== launch =======================================
extern "C" void kernel_launch(void* const* d_in, const int* in_sizes, int n_in,
                              void* d_out, int out_size)
{
    const float* x       = (const float*)d_in[0];
    const int*   ei32    = (const int*)d_in[1];     // int32 view; probe decides layout
    const float* w_ih    = (const float*)d_in[2];
    const float* w_hh    = (const float*)d_in[3];
    const float* b_ih    = (const float*)d_in[4];
    const float* b_hh    = (const float*)d_in[5];
    const float* gat_w   = (const float*)d_in[6];
    const float* att_src = (const float*)d_in[7];
    const float* att_dst = (const float*)d_in[8];
    const float* gat_b   = (const float*)d_in[9];
    const float* lin_w   = (const float*)d_in[10];
    const float* lin_b   = (const float*)d_in[11];
    float*       out     = (float*)d_out;

    detect_kernel<<<1, 32>>>(ei32);
    lstm_kernel<<<Nn / NB, 256>>>(x, w_ih, w_hh, b_ih, b_hh,
                                  gat_w, att_src, att_dst);
    edge_sum_kernel<<<(ETOT * 8 + 255) / 256, 256>>>(ei32);
    final_kernel<<<(Nn * 16 + 255) / 256, 256>>>(gat_b, lin_w, lin_b, out);
}

// round 16
// speedup vs baseline: 1.0536x; 1.0536x over previous
#include <cuda_runtime.h>
#include <cuda_fp16.h>
#include <math.h>

// Problem constants
#define Nn   100000
#define Tt   64
#define Ee   1000000
#define ETOT (Ee + Nn)    // edges + self loops
#define NB   32           // nodes per LSTM block
#define HW   36           // hsh row stride in 32-bit words
#define HS   (NB * HW)    // one h buffer in words

// -------- scratch (device globals; no allocations allowed) ----------
__device__ __half2 g_xh2[Nn * 64];   // GAT features, word p = (head p/32, dims 2p%64)
__device__ __half2 g_acc2[Nn * 64];  // weighted message accumulator (fp16x2)
__device__ float   g_asrc[Nn * 2];
__device__ float   g_adst[Nn * 2];
__device__ float   g_z[Nn * 2];      // segment sum (fp32)
__device__ int     g_estride;        // 1 if edge_index is int32, 2 if int64
__device__ int     g_eoff;           // offset (in int32 words) of dst row

// ==================== edge dtype probe =============================
__global__ void detect_kernel(const int* __restrict__ ei32)
{
    if (threadIdx.x == 0 && blockIdx.x == 0) {
        bool all0 = true;
        #pragma unroll
        for (int i = 1; i < 64; i += 2) all0 &= (ei32[i] == 0);
        g_estride = all0 ? 2 : 1;
        g_eoff    = all0 ? 2 * Ee : Ee;
    }
}

// ==================== helpers ======================================
__device__ __forceinline__ unsigned tanh2(unsigned x)
{
    unsigned y;
    asm("tanh.approx.f16x2 %0, %1;" : "=r"(y) : "r"(x));
    return y;
}
__device__ __forceinline__ __half2 u2h(unsigned u) { return *reinterpret_cast<__half2*>(&u); }
__device__ __forceinline__ unsigned h2u(__half2 h) { return *reinterpret_cast<unsigned*>(&h); }

// fp16x2 sigmoid: 0.5 + 0.5*tanh(0.5*x)
__device__ __forceinline__ __half2 sig2(unsigned u, __half2 half05)
{
    __half2 x = __hmul2(u2h(u), half05);
    return __hfma2(u2h(tanh2(h2u(x))), half05, half05);
}

__device__ __forceinline__ unsigned f2h2u(float a, float b)
{
    __half2 h = __floats2half2_rn(a, b);
    return *reinterpret_cast<unsigned*>(&h);
}

// m16n8k16, fp16 in / fp16 accum. D regs = 2x fp16x2 (rows grp, grp+8).
__device__ __forceinline__ void mma_f16acc(unsigned& c0, unsigned& c1,
                                           unsigned a0, unsigned a1, unsigned a2, unsigned a3,
                                           unsigned b0, unsigned b1)
{
    asm("mma.sync.aligned.m16n8k16.row.col.f16.f16.f16.f16 "
        "{%0,%1}, {%2,%3,%4,%5}, {%6,%7}, {%0,%1};"
        : "+r"(c0), "+r"(c1)
        : "r"(a0), "r"(a1), "r"(a2), "r"(a3), "r"(b0), "r"(b1));
}

// m16n8k16, fp16 in / fp32 accum.
__device__ __forceinline__ void mma_f32acc(float& c0, float& c1, float& c2, float& c3,
                                           unsigned a0, unsigned a1, unsigned a2, unsigned a3,
                                           unsigned b0, unsigned b1)
{
    asm("mma.sync.aligned.m16n8k16.row.col.f32.f16.f16.f32 "
        "{%0,%1,%2,%3}, {%4,%5,%6,%7}, {%8,%9}, {%0,%1,%2,%3};"
        : "+f"(c0), "+f"(c1), "+f"(c2), "+f"(c3)
        : "r"(a0), "r"(a1), "r"(a2), "r"(a3), "r"(b0), "r"(b1));
}

// ==================== LSTM + fused GAT transform ===================
// 256 threads = 8 warps, 32 nodes/block. Main loop: branch-free fp16
// m16n8k16 recurrence at the fallback-HMMA ceiling (R14 config).
// Epilogue: final h (in MMA A-layout in smem) -> xh = h @ gat_w^T
// via fp32-accum MMAs + attention dots.
__global__ void __launch_bounds__(256, 2)
lstm_kernel(const float* __restrict__ x, const float* __restrict__ w_ih,
            const float* __restrict__ w_hh, const float* __restrict__ b_ih,
            const float* __restrict__ b_hh, const float* __restrict__ gat_w,
            const float* __restrict__ att_src, const float* __restrict__ att_dst)
{
    __shared__ unsigned xsh[Tt * NB * 2];   // broadcast half2 per (t, n, d)
    __shared__ unsigned hsh[2 * HS];        // double-buffered h, fp16x2 words
    __shared__ float    sm_as[2][NB];       // attention partial sums
    __shared__ float    sm_ad[2][NB];

    const int tid  = threadIdx.x;
    const int base = blockIdx.x * NB;
    const int wid  = tid >> 5, lane = tid & 31;
    const int grp  = lane >> 2, tig = lane & 3;

    for (int i = tid; i < NB * Tt * 2; i += 256) {
        int n = i >> 7;
        int r = i & 127;
        float v = x[(size_t)(base + n) * 128 + r];
        xsh[(r >> 1) * (NB * 2) + n * 2 + (r & 1)] = h2u(__float2half2_rn(v));
    }
    for (int i = tid; i < 2 * HS; i += 256) hsh[i] = 0u;
    if (tid < 64) {
        sm_as[tid >> 5][tid & 31] = 0.f;
        sm_ad[tid >> 5][tid & 31] = 0.f;
    }

    const int j0 = wid * 8 + 2 * tig;

    unsigned bias2[4], wa2[4], wb2[4];
    #pragma unroll
    for (int q = 0; q < 4; ++q) {
        int g = q * 64 + j0;
        bias2[q] = f2h2u(b_ih[g] + b_hh[g], b_ih[g + 1] + b_hh[g + 1]);
        wa2[q]   = f2h2u(w_ih[g * 2],     w_ih[(g + 1) * 2]);
        wb2[q]   = f2h2u(w_ih[g * 2 + 1], w_ih[(g + 1) * 2 + 1]);
    }

    unsigned bf[4][4][2];
    #pragma unroll
    for (int q = 0; q < 4; ++q) {
        const float* wr = &w_hh[(size_t)(q * 64 + wid * 8 + grp) * 64];
        #pragma unroll
        for (int kt = 0; kt < 4; ++kt) {
            int k = kt * 16 + 2 * tig;
            bf[q][kt][0] = f2h2u(wr[k],     wr[k + 1]);
            bf[q][kt][1] = f2h2u(wr[k + 8], wr[k + 9]);
        }
    }

    const int rp[4] = { grp * HW + tig,        (grp + 8) * HW + tig,
                        (grp + 16) * HW + tig, (grp + 24) * HW + tig };
    const int sp[4] = { grp * HW + wid * 4 + tig,        (grp + 8) * HW + wid * 4 + tig,
                        (grp + 16) * HW + wid * 4 + tig, (grp + 24) * HW + wid * 4 + tig };

    const __half2 half05 = __float2half2_rn(0.5f);
    __half2 creg[4];
    #pragma unroll
    for (int r = 0; r < 4; ++r) creg[r] = __float2half2_rn(0.f);

    __syncthreads();

    for (int t = 0; t < Tt; ++t) {
        const unsigned* rb   = &hsh[(t & 1) * HS];
        unsigned*       wbuf = &hsh[((t + 1) & 1) * HS];

        unsigned xl[4], xh[4];
        #pragma unroll
        for (int m = 0; m < 4; ++m) {
            int n = grp + 8 * m;
            xl[m] = xsh[t * (NB * 2) + n * 2];
            xh[m] = xsh[t * (NB * 2) + n * 2 + 1];
        }
        unsigned c[4][4];
        #pragma unroll
        for (int q = 0; q < 4; ++q) {
            #pragma unroll
            for (int m = 0; m < 4; ++m)
                c[q][m] = h2u(__hfma2(u2h(wb2[q]), u2h(xh[m]),
                              __hfma2(u2h(wa2[q]), u2h(xl[m]), u2h(bias2[q]))));
        }
        #pragma unroll
        for (int kt = 0; kt < 4; ++kt) {
            unsigned a0 = rb[rp[0] + kt * 8];
            unsigned a1 = rb[rp[1] + kt * 8];
            unsigned a2 = rb[rp[0] + kt * 8 + 4];
            unsigned a3 = rb[rp[1] + kt * 8 + 4];
            unsigned a4 = rb[rp[2] + kt * 8];
            unsigned a5 = rb[rp[3] + kt * 8];
            unsigned a6 = rb[rp[2] + kt * 8 + 4];
            unsigned a7 = rb[rp[3] + kt * 8 + 4];
            #pragma unroll
            for (int q = 0; q < 4; ++q) {
                mma_f16acc(c[q][0], c[q][1], a0, a1, a2, a3,
                           bf[q][kt][0], bf[q][kt][1]);
                mma_f16acc(c[q][2], c[q][3], a4, a5, a6, a7,
                           bf[q][kt][0], bf[q][kt][1]);
            }
        }

        #pragma unroll
        for (int r = 0; r < 4; ++r) {
            __half2 i2 = sig2(c[0][r], half05);
            __half2 f2 = sig2(c[1][r], half05);
            __half2 g2 = u2h(tanh2(c[2][r]));
            __half2 o2 = sig2(c[3][r], half05);
            creg[r] = __hfma2(f2, creg[r], __hmul2(i2, g2));
            wbuf[sp[r]] = h2u(__hmul2(o2, u2h(tanh2(h2u(creg[r])))));
        }
        __syncthreads();
    }

    // ============ fused GAT transform epilogue =====================
    const unsigned* hb = &hsh[0];   // final h buffer (Tt & 1) = 0

    unsigned bg[2][4][2];
    #pragma unroll
    for (int nt = 0; nt < 2; ++nt) {
        const float* wr = &gat_w[(size_t)(wid * 16 + nt * 8 + grp) * 64];
        #pragma unroll
        for (int kt = 0; kt < 4; ++kt) {
            int k = kt * 16 + 2 * tig;
            bg[nt][kt][0] = f2h2u(wr[k],     wr[k + 1]);
            bg[nt][kt][1] = f2h2u(wr[k + 8], wr[k + 9]);
        }
    }

    float cx[2][2][4];
    #pragma unroll
    for (int nt = 0; nt < 2; ++nt)
        #pragma unroll
        for (int mt = 0; mt < 2; ++mt)
            #pragma unroll
            for (int e = 0; e < 4; ++e) cx[nt][mt][e] = 0.f;

    #pragma unroll
    for (int kt = 0; kt < 4; ++kt) {
        unsigned a0 = hb[rp[0] + kt * 8];
        unsigned a1 = hb[rp[1] + kt * 8];
        unsigned a2 = hb[rp[0] + kt * 8 + 4];
        unsigned a3 = hb[rp[1] + kt * 8 + 4];
        unsigned a4 = hb[rp[2] + kt * 8];
        unsigned a5 = hb[rp[3] + kt * 8];
        unsigned a6 = hb[rp[2] + kt * 8 + 4];
        unsigned a7 = hb[rp[3] + kt * 8 + 4];
        #pragma unroll
        for (int nt = 0; nt < 2; ++nt) {
            mma_f32acc(cx[nt][0][0], cx[nt][0][1], cx[nt][0][2], cx[nt][0][3],
                       a0, a1, a2, a3, bg[nt][kt][0], bg[nt][kt][1]);
            mma_f32acc(cx[nt][1][0], cx[nt][1][1], cx[nt][1][2], cx[nt][1][3],
                       a4, a5, a6, a7, bg[nt][kt][0], bg[nt][kt][1]);
        }
    }

    const int hg0  = wid * 16 + 2 * tig;
    const int hg1  = hg0 + 8;
    const int head = wid >> 2;
    const int p0   = head * 32 + ((hg0 & 63) >> 1);
    const int p1   = head * 32 + ((hg1 & 63) >> 1);
    const float2 as0 = make_float2(att_src[hg0], att_src[hg0 + 1]);
    const float2 as1 = make_float2(att_src[hg1], att_src[hg1 + 1]);
    const float2 ad0 = make_float2(att_dst[hg0], att_dst[hg0 + 1]);
    const float2 ad1 = make_float2(att_dst[hg1], att_dst[hg1 + 1]);
    const __half2 hz = __float2half2_rn(0.f);

    #pragma unroll
    for (int mt = 0; mt < 2; ++mt) {
        #pragma unroll
        for (int r = 0; r < 2; ++r) {
            int node = mt * 16 + grp + 8 * r;
            size_t n = base + node;
            float v00 = cx[0][mt][2 * r], v01 = cx[0][mt][2 * r + 1];
            float v10 = cx[1][mt][2 * r], v11 = cx[1][mt][2 * r + 1];
            g_xh2[n * 64 + p0]  = __floats2half2_rn(v00, v01);
            g_xh2[n * 64 + p1]  = __floats2half2_rn(v10, v11);
            g_acc2[n * 64 + p0] = hz;
            g_acc2[n * 64 + p1] = hz;
            float ps = v00 * as0.x + v01 * as0.y + v10 * as1.x + v11 * as1.y;
            float pd = v00 * ad0.x + v01 * ad0.y + v10 * ad1.x + v11 * ad1.y;
            ps += __shfl_xor_sync(0xffffffffu, ps, 1);
            ps += __shfl_xor_sync(0xffffffffu, ps, 2);
            pd += __shfl_xor_sync(0xffffffffu, pd, 1);
            pd += __shfl_xor_sync(0xffffffffu, pd, 2);
            if (tig == 0) {
                atomicAdd(&sm_as[head][node], ps);
                atomicAdd(&sm_ad[head][node], pd);
            }
        }
    }
    __syncthreads();
    if (tid < 64) {
        int node = tid & 31, hd = tid >> 5;
        size_t n = base + node;
        g_asrc[n * 2 + hd] = sm_as[hd][node];
        g_adst[n * 2 + hd] = sm_ad[hd][node];
        g_z[n * 2 + hd]    = 0.f;
    }
}

// ==================== GAT: exp-sum + weighted messages =============
// 8 lanes/edge; each lane owns one 16B chunk per head (2 independent
// v4.f16x2 reduction chains).
__global__ void __launch_bounds__(256)
edge_sum_kernel(const int* __restrict__ ei32)
{
    int e   = (blockIdx.x * 256 + threadIdx.x) >> 3;
    int sub = threadIdx.x & 7;
    if (e >= ETOT) return;
    const int st = g_estride, of = g_eoff;
    int s, d;
    if (e < Ee) { s = ei32[(size_t)e * st]; d = ei32[(size_t)of + (size_t)e * st]; }
    else        { s = d = e - Ee; }

    float e0 = g_asrc[s * 2]     + g_adst[d * 2];
    float e1 = g_asrc[s * 2 + 1] + g_adst[d * 2 + 1];
    e0 = e0 > 0.f ? e0 : 0.2f * e0;
    e1 = e1 > 0.f ? e1 : 0.2f * e1;
    float w0 = __expf(e0);
    float w1 = __expf(e1);
    if (sub == 0) atomicAdd(&g_z[d * 2],     w0);
    if (sub == 1) atomicAdd(&g_z[d * 2 + 1], w1);

    __half2 c0 = __float2half2_rn(w0);
    __half2 c1 = __float2half2_rn(w1);
    const uint4* xb = (const uint4*)(g_xh2 + (size_t)s * 64);
    uint4 xv0 = xb[sub];
    uint4 xv1 = xb[8 + sub];
    unsigned m00 = h2u(__hmul2(u2h(xv0.x), c0));
    unsigned m01 = h2u(__hmul2(u2h(xv0.y), c0));
    unsigned m02 = h2u(__hmul2(u2h(xv0.z), c0));
    unsigned m03 = h2u(__hmul2(u2h(xv0.w), c0));
    unsigned m10 = h2u(__hmul2(u2h(xv1.x), c1));
    unsigned m11 = h2u(__hmul2(u2h(xv1.y), c1));
    unsigned m12 = h2u(__hmul2(u2h(xv1.z), c1));
    unsigned m13 = h2u(__hmul2(u2h(xv1.w), c1));
    __half2* ap0 = g_acc2 + (size_t)d * 64 + sub * 4;
    __half2* ap1 = ap0 + 32;
    asm volatile("red.global.add.noftz.v4.f16x2 [%0], {%1,%2,%3,%4};"
                 :: "l"(ap0), "r"(m00), "r"(m01), "r"(m02), "r"(m03) : "memory");
    asm volatile("red.global.add.noftz.v4.f16x2 [%0], {%1,%2,%3,%4};"
                 :: "l"(ap1), "r"(m10), "r"(m11), "r"(m12), "r"(m13) : "memory");
}

// ==================== finalize (16 lanes/node) =====================
__global__ void __launch_bounds__(256)
final_kernel(const float* __restrict__ gat_b, const float* __restrict__ lin_w,
             const float* __restrict__ lin_b, float* __restrict__ out)
{
    int idx = blockIdx.x * 256 + threadIdx.x;
    int n   = idx >> 4;
    int sub = idx & 15;
    if (n >= Nn) return;
    float r0 = 0.5f / g_z[n * 2];
    float r1 = 0.5f / g_z[n * 2 + 1];
    const __half2* ac = g_acc2 + (size_t)n * 64;
    float2 a00 = __half22float2(ac[sub]);
    float2 a01 = __half22float2(ac[16 + sub]);
    float2 a10 = __half22float2(ac[32 + sub]);
    float2 a11 = __half22float2(ac[48 + sub]);
    float2 gb0 = ((const float2*)gat_b)[sub];
    float2 gb1 = ((const float2*)gat_b)[16 + sub];
    float v0 = a00.x * r0 + a10.x * r1 + gb0.x;
    float v1 = a00.y * r0 + a10.y * r1 + gb0.y;
    float v2 = a01.x * r0 + a11.x * r1 + gb1.x;
    float v3 = a01.y * r0 + a11.y * r1 + gb1.y;
    v0 = v0 > 0.f ? v0 : 0.f;
    v1 = v1 > 0.f ? v1 : 0.f;
    v2 = v2 > 0.f ? v2 : 0.f;
    v3 = v3 > 0.f ? v3 : 0.f;
    float2 l00 = ((const float2*)lin_w)[sub];
    float2 l01 = ((const float2*)lin_w)[16 + sub];
    float2 l10 = ((const float2*)lin_w)[32 + sub];
    float2 l11 = ((const float2*)lin_w)[48 + sub];
    float y0 = v0 * l00.x + v1 * l00.y + v2 * l01.x + v3 * l01.y;
    float y1 = v0 * l10.x + v1 * l10.y + v2 * l11.x + v3 * l11.y;
    #pragma unroll
    for (int off = 8; off; off >>= 1) {
        y0 += __shfl_down_sync(0xffffffffu, y0, off, 16);
        y1 += __shfl_down_sync(0xffffffffu, y1, off, 16);
    }
    if (sub == 0) {
        out[n * 2]     = 1.f / (1.f + __expf(-(y0 + lin_b[0])));
        out[n * 2 + 1] = 1.f / (1.f + __expf(-(y1 + lin_b[1])));
    }
}

// ==================== launch =======================================
extern "C" void kernel_launch(void* const* d_in, const int* in_sizes, int n_in,
                              void* d_out, int out_size)
{
    const float* x       = (const float*)d_in[0];
    const int*   ei32    = (const int*)d_in[1];     // int32 view; probe decides layout
    const float* w_ih    = (const float*)d_in[2];
    const float* w_hh    = (const float*)d_in[3];
    const float* b_ih    = (const float*)d_in[4];
    const float* b_hh    = (const float*)d_in[5];
    const float* gat_w   = (const float*)d_in[6];
    const float* att_src = (const float*)d_in[7];
    const float* att_dst = (const float*)d_in[8];
    const float* gat_b   = (const float*)d_in[9];
    const float* lin_w   = (const float*)d_in[10];
    const float* lin_b   = (const float*)d_in[11];
    float*       out     = (float*)d_out;

    detect_kernel<<<1, 32>>>(ei32);
    lstm_kernel<<<Nn / NB, 256>>>(x, w_ih, w_hh, b_ih, b_hh,
                                  gat_w, att_src, att_dst);
    edge_sum_kernel<<<(ETOT * 8 + 255) / 256, 256>>>(ei32);
    final_kernel<<<(Nn * 16 + 255) / 256, 256>>>(gat_b, lin_w, lin_b, out);
}